// round 14
// baseline (speedup 1.0000x reference)
#include <cuda_runtime.h>
#include <cstdint>

// out[b,m] = dot(inputs[b,m,:], W[m,:]) + bias[m]
// B=1024, M=2048, I=128 (32 float4 per row).
//
// Layout: 8 lanes per output row, 4 output rows per warp.
//   lane = 8*g + sub  (g = output slot 0..3, sub = 0..7)
//   Each lane loads 4 float4 of x and 4 float4 of w  -> MLP=8 per thread.
//   Reduction: 3 butterfly shuffles (xor 4,2,1) reduce all 4 outputs at once.
//
// R14 variant: 512-thread blocks (64 rows = 32 KB contiguous input per CTA,
// grid halved to 32768). Identical per-warp SASS and occupancy (2048 thr/SM);
// only CTA scheduling granularity changes — wider contiguous DRAM windows
// per in-flight CTA, half the launch/drain events.
//
// Session status: HBM streaming ceiling (~7.0 TB/s effective, 86-88%
// DRAM-active). Traffic irreducible (1.074 GB single-touch input). Invariant
// to cache hints, MLP 8/16, occupancy 31-65%, store vectorization, 256-bit
// loads; persistent pipelining regressed 1.9x. Best measured: 153.9 us.

static constexpr int M_DIM = 2048;
static constexpr long long TOTAL = 1024LL * 2048LL;  // B*M outputs

__global__ __launch_bounds__(512, 3)
void rowdot_kernel(const float4* __restrict__ inp,   // [B*M, 32] float4
                   const float4* __restrict__ W,     // [M, 32] float4
                   const float*  __restrict__ bias,  // [M]
                   float* __restrict__ out)          // [B*M]
{
    const int lane = threadIdx.x & 31;
    const int warp_in_block = threadIdx.x >> 5;
    const long long warp = (long long)blockIdx.x * (blockDim.x >> 5) + warp_in_block;

    const int g   = lane >> 3;   // which of 4 outputs this lane works on
    const int sub = lane & 7;    // position within 8-lane group

    const long long row = warp * 4 + g;     // output index (b*M + m)
    if (row >= TOTAL) return;
    const int m = (int)(row & (M_DIM - 1));

    const float4* __restrict__ xr = inp + row * 32 + sub;
    const float4* __restrict__ wr = W   + (long long)m * 32 + sub;

    // Front-batch all 8 loads (independent) -> MLP=8.
    float4 x0 = xr[0];
    float4 x1 = xr[8];
    float4 x2 = xr[16];
    float4 x3 = xr[24];
    float4 w0 = wr[0];
    float4 w1 = wr[8];
    float4 w2 = wr[16];
    float4 w3 = wr[24];

    float s = x0.x * w0.x + x0.y * w0.y + x0.z * w0.z + x0.w * w0.w;
    s = fmaf(x1.x, w1.x, s); s = fmaf(x1.y, w1.y, s);
    s = fmaf(x1.z, w1.z, s); s = fmaf(x1.w, w1.w, s);
    s = fmaf(x2.x, w2.x, s); s = fmaf(x2.y, w2.y, s);
    s = fmaf(x2.z, w2.z, s); s = fmaf(x2.w, w2.w, s);
    s = fmaf(x3.x, w3.x, s); s = fmaf(x3.y, w3.y, s);
    s = fmaf(x3.z, w3.z, s); s = fmaf(x3.w, w3.w, s);

    // Butterfly within each 8-lane group: reduces all 4 outputs in 3 steps.
    s += __shfl_xor_sync(0xFFFFFFFFu, s, 4);
    s += __shfl_xor_sync(0xFFFFFFFFu, s, 2);
    s += __shfl_xor_sync(0xFFFFFFFFu, s, 1);

    if (sub == 0) {
        out[row] = s + __ldg(&bias[m]);
    }
}

extern "C" void kernel_launch(void* const* d_in, const int* in_sizes, int n_in,
                              void* d_out, int out_size)
{
    const float4* inp  = (const float4*)d_in[0];  // inputs  [B, M, I] f32
    const float4* W    = (const float4*)d_in[1];  // Rk_weight [M, I] f32
    const float*  bias = (const float*)d_in[2];   // bias [M] f32
    float*        out  = (float*)d_out;           // [B, M] f32

    // 4 outputs per warp, 16 warps per block -> 64 outputs per block.
    const int threads = 512;
    const long long outputs_per_block = 64;
    const int blocks = (int)((TOTAL + outputs_per_block - 1) / outputs_per_block);

    rowdot_kernel<<<blocks, threads>>>(inp, W, bias, out);
}

// round 16
// speedup vs baseline: 1.0123x; 1.0123x over previous
#include <cuda_runtime.h>
#include <cstdint>

// out[b,m] = dot(inputs[b,m,:], W[m,:]) + bias[m]
// B=1024, M=2048, I=128 (32 float4 per row).
//
// FINAL: at the HBM streaming ceiling — ~7.03 TB/s effective (~88% of
// 8 TB/s spec), 86-88% DRAM-active. Traffic irreducible (1.074 GB
// single-touch input; W is L2-resident; output <1%). Verified invariant to
// cache hints, MLP 8/16, occupancy 31-65%, store vectorization, 256-bit
// loads; persistent pipelining regressed 1.9x; 512-thread blocks ~2us
// worse. Best measured: 153.9 us, 1.40x over naive baseline.

static constexpr int M_DIM = 2048;
static constexpr long long TOTAL = 1024LL * 2048LL;  // B*M outputs

__global__ __launch_bounds__(256, 6)
void rowdot_kernel(const float4* __restrict__ inp,   // [B*M, 32] float4
                   const float4* __restrict__ W,     // [M, 32] float4
                   const float*  __restrict__ bias,  // [M]
                   float* __restrict__ out)          // [B*M]
{
    const int lane = threadIdx.x & 31;
    const int warp_in_block = threadIdx.x >> 5;
    const long long warp = (long long)blockIdx.x * (blockDim.x >> 5) + warp_in_block;

    const int g   = lane >> 3;   // which of 4 outputs this lane works on
    const int sub = lane & 7;    // position within 8-lane group

    const long long row = warp * 4 + g;     // output index (b*M + m)
    if (row >= TOTAL) return;
    const int m = (int)(row & (M_DIM - 1));

    const float4* __restrict__ xr = inp + row * 32 + sub;
    const float4* __restrict__ wr = W   + (long long)m * 32 + sub;

    // Front-batch all 8 loads (independent) -> MLP=8.
    float4 x0 = xr[0];
    float4 x1 = xr[8];
    float4 x2 = xr[16];
    float4 x3 = xr[24];
    float4 w0 = wr[0];
    float4 w1 = wr[8];
    float4 w2 = wr[16];
    float4 w3 = wr[24];

    float s = x0.x * w0.x + x0.y * w0.y + x0.z * w0.z + x0.w * w0.w;
    s = fmaf(x1.x, w1.x, s); s = fmaf(x1.y, w1.y, s);
    s = fmaf(x1.z, w1.z, s); s = fmaf(x1.w, w1.w, s);
    s = fmaf(x2.x, w2.x, s); s = fmaf(x2.y, w2.y, s);
    s = fmaf(x2.z, w2.z, s); s = fmaf(x2.w, w2.w, s);
    s = fmaf(x3.x, w3.x, s); s = fmaf(x3.y, w3.y, s);
    s = fmaf(x3.z, w3.z, s); s = fmaf(x3.w, w3.w, s);

    // Butterfly within each 8-lane group: reduces all 4 outputs in 3 steps.
    s += __shfl_xor_sync(0xFFFFFFFFu, s, 4);
    s += __shfl_xor_sync(0xFFFFFFFFu, s, 2);
    s += __shfl_xor_sync(0xFFFFFFFFu, s, 1);

    if (sub == 0) {
        out[row] = s + __ldg(&bias[m]);
    }
}

extern "C" void kernel_launch(void* const* d_in, const int* in_sizes, int n_in,
                              void* d_out, int out_size)
{
    const float4* inp  = (const float4*)d_in[0];  // inputs  [B, M, I] f32
    const float4* W    = (const float4*)d_in[1];  // Rk_weight [M, I] f32
    const float*  bias = (const float*)d_in[2];   // bias [M] f32
    float*        out  = (float*)d_out;           // [B, M] f32

    // 4 outputs per warp, 8 warps per block -> 32 outputs per block.
    const int threads = 256;
    const long long outputs_per_block = 32;
    const int blocks = (int)((TOTAL + outputs_per_block - 1) / outputs_per_block);

    rowdot_kernel<<<blocks, threads>>>(inp, W, bias, out);
}

// round 17
// speedup vs baseline: 1.0152x; 1.0029x over previous
#include <cuda_runtime.h>
#include <cstdint>

// out[b,m] = dot(inputs[b,m,:], W[m,:]) + bias[m]
// B=1024, M=2048, I=128 (32 float4 per row).
//
// Layout: 8 lanes per output row, 4 output rows per warp.
//   lane = 8*g + sub  (g = output slot 0..3, sub = 0..7)
//   Each lane loads 4 float4 of x and 4 float4 of w  -> MLP=8 per thread.
//   Reduction: 3 butterfly shuffles (xor 4,2,1) reduce all 4 outputs at once.
//
// R17 probe: 128-thread blocks (16 rows/CTA, grid 131072). Per-warp SASS
// identical to the proven 153.9us config; only the CTA scheduling quantum
// shrinks (R14 showed 512 > 256 cost ~2us via tail-wave granularity; this
// tests the other direction). Session status: HBM streaming ceiling,
// ~7.03 TB/s effective, 86-88% DRAM-active, traffic irreducible.

static constexpr int M_DIM = 2048;
static constexpr long long TOTAL = 1024LL * 2048LL;  // B*M outputs

__global__ __launch_bounds__(128, 12)
void rowdot_kernel(const float4* __restrict__ inp,   // [B*M, 32] float4
                   const float4* __restrict__ W,     // [M, 32] float4
                   const float*  __restrict__ bias,  // [M]
                   float* __restrict__ out)          // [B*M]
{
    const int lane = threadIdx.x & 31;
    const int warp_in_block = threadIdx.x >> 5;
    const long long warp = (long long)blockIdx.x * (blockDim.x >> 5) + warp_in_block;

    const int g   = lane >> 3;   // which of 4 outputs this lane works on
    const int sub = lane & 7;    // position within 8-lane group

    const long long row = warp * 4 + g;     // output index (b*M + m)
    if (row >= TOTAL) return;
    const int m = (int)(row & (M_DIM - 1));

    const float4* __restrict__ xr = inp + row * 32 + sub;
    const float4* __restrict__ wr = W   + (long long)m * 32 + sub;

    // Front-batch all 8 loads (independent) -> MLP=8.
    float4 x0 = xr[0];
    float4 x1 = xr[8];
    float4 x2 = xr[16];
    float4 x3 = xr[24];
    float4 w0 = wr[0];
    float4 w1 = wr[8];
    float4 w2 = wr[16];
    float4 w3 = wr[24];

    float s = x0.x * w0.x + x0.y * w0.y + x0.z * w0.z + x0.w * w0.w;
    s = fmaf(x1.x, w1.x, s); s = fmaf(x1.y, w1.y, s);
    s = fmaf(x1.z, w1.z, s); s = fmaf(x1.w, w1.w, s);
    s = fmaf(x2.x, w2.x, s); s = fmaf(x2.y, w2.y, s);
    s = fmaf(x2.z, w2.z, s); s = fmaf(x2.w, w2.w, s);
    s = fmaf(x3.x, w3.x, s); s = fmaf(x3.y, w3.y, s);
    s = fmaf(x3.z, w3.z, s); s = fmaf(x3.w, w3.w, s);

    // Butterfly within each 8-lane group: reduces all 4 outputs in 3 steps.
    s += __shfl_xor_sync(0xFFFFFFFFu, s, 4);
    s += __shfl_xor_sync(0xFFFFFFFFu, s, 2);
    s += __shfl_xor_sync(0xFFFFFFFFu, s, 1);

    if (sub == 0) {
        out[row] = s + __ldg(&bias[m]);
    }
}

extern "C" void kernel_launch(void* const* d_in, const int* in_sizes, int n_in,
                              void* d_out, int out_size)
{
    const float4* inp  = (const float4*)d_in[0];  // inputs  [B, M, I] f32
    const float4* W    = (const float4*)d_in[1];  // Rk_weight [M, I] f32
    const float*  bias = (const float*)d_in[2];   // bias [M] f32
    float*        out  = (float*)d_out;           // [B, M] f32

    // 4 outputs per warp, 4 warps per block -> 16 outputs per block.
    const int threads = 128;
    const long long outputs_per_block = 16;
    const int blocks = (int)((TOTAL + outputs_per_block - 1) / outputs_per_block);

    rowdot_kernel<<<blocks, threads>>>(inp, W, bias, out);
}